// round 16
// baseline (speedup 1.0000x reference)
#include <cuda_runtime.h>
#include <cuda_bf16.h>
#include <math.h>

#define NTOK 4096
#define BD 16      // q/k projection dim
#define CC 128     // value channels
#define BM 64      // query tile
#define BN 64      // key tile
#define NB 4       // batch
#define NT (NTOK / BN)   // 64 key tiles

typedef unsigned long long u64;
typedef unsigned int u32;

// ---------------- packed f32x2 helpers ----------------
__device__ __forceinline__ u64 pk2(float lo, float hi) {
    u64 r;
    asm("mov.b64 %0, {%1, %2};" : "=l"(r) : "r"(__float_as_uint(lo)), "r"(__float_as_uint(hi)));
    return r;
}
__device__ __forceinline__ void upk2(float& lo, float& hi, u64 v) {
    u32 a, b;
    asm("mov.b64 {%0, %1}, %2;" : "=r"(a), "=r"(b) : "l"(v));
    lo = __uint_as_float(a); hi = __uint_as_float(b);
}
__device__ __forceinline__ void fma2(u64& d, u64 a, u64 b) {
    asm("fma.rn.f32x2 %0, %1, %2, %3;" : "=l"(d) : "l"(a), "l"(b), "l"(d));
}
__device__ __forceinline__ u64 d2u(double d) { return (u64)__double_as_longlong(d); }

// pack two f32 -> bf16x2 (lo at low half)
__device__ __forceinline__ u32 cvt2bf(float lo, float hi) {
    u32 r;
    asm("cvt.rn.bf16x2.f32 %0, %1, %2;" : "=r"(r) : "f"(hi), "f"(lo));
    return r;
}

// ---------------- cp.async ----------------
__device__ __forceinline__ void cp16s(u32 ds, const void* src) {
    asm volatile("cp.async.cg.shared.global [%0], [%1], 16;" :: "r"(ds), "l"(src));
}
#define CP_COMMIT() asm volatile("cp.async.commit_group;" ::: "memory")
#define CP_WAIT1()  asm volatile("cp.async.wait_group 1;" ::: "memory")

// ---------------- ldmatrix / mma.sync ----------------
#define LDSM_X4(r0, r1, r2, r3, addr) \
    asm volatile("ldmatrix.sync.aligned.m8n8.x4.shared.b16 {%0,%1,%2,%3}, [%4];" \
                 : "=r"(r0), "=r"(r1), "=r"(r2), "=r"(r3) : "r"(addr))
#define LDSM_X4T(r0, r1, r2, r3, addr) \
    asm volatile("ldmatrix.sync.aligned.m8n8.x4.trans.shared.b16 {%0,%1,%2,%3}, [%4];" \
                 : "=r"(r0), "=r"(r1), "=r"(r2), "=r"(r3) : "r"(addr))
#define MMA_BF16(c0, c1, c2, c3, a0, a1, a2, a3, b0, b1) \
    asm volatile("mma.sync.aligned.m16n8k16.row.col.f32.bf16.bf16.f32 " \
                 "{%0,%1,%2,%3}, {%4,%5,%6,%7}, {%8,%9}, {%0,%1,%2,%3};" \
                 : "+f"(c0), "+f"(c1), "+f"(c2), "+f"(c3) \
                 : "r"(a0), "r"(a1), "r"(a2), "r"(a3), "r"(b0), "r"(b1))

// scratch (allocation-free rule: __device__ globals)
__device__ __align__(16) float g_q[NB * NTOK * BD];
__device__ __align__(16) __nv_bfloat16 g_khi[NB * BD * NTOK];  // [b][d][tok]
__device__ __align__(16) __nv_bfloat16 g_klo[NB * BD * NTOK];  // [b][d][tok]
__device__ __align__(16) __nv_bfloat16 g_vb[NB * NTOK * CC];   // token-major bf16 V

// ---------------------------------------------------------------------------
// fused projections (FFMA2 inner loops).
// blockIdx.x < 16  -> q/k projection (one token per thread, packed weights)
// blockIdx.x >= 16 -> v projection -> token-major bf16 (packed channel pairs)
// ---------------------------------------------------------------------------
__global__ void __launch_bounds__(256)
proj_kernel(const float* __restrict__ x,
            const float* __restrict__ Wq, const float* __restrict__ bq,
            const float* __restrict__ Wk, const float* __restrict__ bk,
            const float* __restrict__ xh,
            const float* __restrict__ Wv, const float* __restrict__ bv)
{
    __shared__ __align__(16) float sbuf[128 * 64 + 16 * 128];
    int tid = threadIdx.x;
    int b = blockIdx.y;

    if (blockIdx.x < 16) {
        // ---------------- q/k projection, packed-pair weights ----------------
        u64* sWqp = (u64*)sbuf;            // [64][8] d-pairs
        u64* sWkp = (u64*)sbuf + 512;      // [64][8]
        float* sb = (float*)((u64*)sbuf + 1024);   // 32 bias floats
        for (int e = tid; e < 512; e += 256) {
            int c = e >> 3, dp = e & 7;
            sWqp[c * 8 + dp] = pk2(Wq[(2 * dp) * 64 + c], Wq[(2 * dp + 1) * 64 + c]);
            sWkp[c * 8 + dp] = pk2(Wk[(2 * dp) * 64 + c], Wk[(2 * dp + 1) * 64 + c]);
        }
        if (tid < 16) { sb[tid] = bq[tid]; sb[16 + tid] = bk[tid]; }
        __syncthreads();

        int n = blockIdx.x * 256 + tid;
        float xc[64];
#pragma unroll
        for (int c = 0; c < 64; ++c) xc[c] = x[((size_t)b * 64 + c) * NTOK + n];

        u64 q2[8], k2[8];
#pragma unroll
        for (int dp = 0; dp < 8; ++dp) {
            q2[dp] = pk2(sb[2 * dp], sb[2 * dp + 1]);
            k2[dp] = pk2(sb[16 + 2 * dp], sb[16 + 2 * dp + 1]);
        }
#pragma unroll
        for (int c = 0; c < 64; ++c) {
            u64 xv2 = pk2(xc[c], xc[c]);
#pragma unroll
            for (int dp = 0; dp < 8; ++dp) {
                fma2(q2[dp], sWqp[c * 8 + dp], xv2);
                fma2(k2[dp], sWkp[c * 8 + dp], xv2);
            }
        }

        float* qo = g_q + ((size_t)b * NTOK + n) * BD;
#pragma unroll
        for (int dp = 0; dp < 8; ++dp) {
            float q0, q1, k0, k1;
            upk2(q0, q1, q2[dp]);
            upk2(k0, k1, k2[dp]);
            qo[2 * dp] = q0; qo[2 * dp + 1] = q1;
            int d0 = 2 * dp, d1 = 2 * dp + 1;
            __nv_bfloat16 kh0 = __float2bfloat16(k0);
            __nv_bfloat16 kh1 = __float2bfloat16(k1);
            g_khi[((size_t)b * BD + d0) * NTOK + n] = kh0;
            g_khi[((size_t)b * BD + d1) * NTOK + n] = kh1;
            g_klo[((size_t)b * BD + d0) * NTOK + n] = __float2bfloat16(k0 - __bfloat162float(kh0));
            g_klo[((size_t)b * BD + d1) * NTOK + n] = __float2bfloat16(k1 - __bfloat162float(kh1));
        }
    } else {
        // ---------------- v projection, packed channel pairs ----------------
        float (*Xs)[64]  = (float (*)[64])sbuf;
        float (*Wt)[128] = (float (*)[128])(sbuf + 8192);
        int n0 = (blockIdx.x - 16) * 64;
        int nl = tid & 63;
        int g  = tid >> 6;

        for (int e = tid; e < 128 * 64; e += 256) {
            int c = e >> 6, nn = e & 63;
            Xs[c][nn] = xh[((size_t)b * 128 + c) * NTOK + n0 + nn];
        }

        u64 acc2[16];
#pragma unroll
        for (int i = 0; i < 16; ++i) acc2[i] = 0ull;

        for (int cc0 = 0; cc0 < 128; cc0 += 16) {
            __syncthreads();
            for (int e = tid; e < 16 * 128; e += 256) {
                int c = e >> 4, cp = e & 15;
                Wt[cp][c] = Wv[c * 128 + cc0 + cp];
            }
            __syncthreads();
#pragma unroll
            for (int cp = 0; cp < 16; ++cp) {
                float xv = Xs[cc0 + cp][nl];
                u64 xv2 = pk2(xv, xv);
                const double2* w2 = (const double2*)&Wt[cp][g * 32];
#pragma unroll
                for (int j = 0; j < 8; ++j) {
                    double2 w = w2[j];
                    fma2(acc2[2 * j],     d2u(w.x), xv2);
                    fma2(acc2[2 * j + 1], d2u(w.y), xv2);
                }
            }
        }

        __nv_bfloat16* vo = g_vb + ((size_t)b * NTOK + n0 + nl) * CC + g * 32;
#pragma unroll
        for (int j = 0; j < 16; ++j) {
            float a0, a1;
            upk2(a0, a1, acc2[j]);
            int c0 = g * 32 + 2 * j;
            *(__nv_bfloat162*)(vo + 2 * j) =
                __floats2bfloat162_rn(a0 + bv[c0], a1 + bv[c0 + 1]);
        }
    }
}

// ---------------------------------------------------------------------------
// flash attention: QK via bf16x3 mma (term-major order, 8-indep chains),
// P in registers, PV mma with ks-outer order (16-indep chains per round).
// 128 threads (4 warps), 2 CTAs/SM.
// ---------------------------------------------------------------------------
#define QH_OFF   0
#define Q_STRB   48                         // bytes per Q row (16 bf16 + pad)
#define QL_OFF   (BM * Q_STRB)              // 3072
#define KH_OFF   (2 * BM * Q_STRB)          // 6144
#define K_STRB   144                        // bytes per K row (64 bf16 + pad)
#define K_BUFB   (16 * K_STRB)              // 2304
#define KL_OFF   (KH_OFF + 2 * K_BUFB)      // 10752
#define V_OFF    (KL_OFF + 2 * K_BUFB)      // 15360
#define V_STRB   272                        // bytes per V row (128 bf16 + pad)
#define V_BUFB   (BN * V_STRB)              // 17408
#define SMEM_BYTES (V_OFF + 2 * V_BUFB)     // 50176  (x2 CTA = 100352)

__global__ void __launch_bounds__(128, 2)
flash_kernel(const float* __restrict__ xh,
             const float* __restrict__ gamma,
             float* __restrict__ out)
{
    extern __shared__ __align__(16) char smb[];
    u32 sb = (u32)__cvta_generic_to_shared(smb);

    int tid  = threadIdx.x;
    int warp = tid >> 5, lane = tid & 31;
    int b  = blockIdx.y;
    int i0 = blockIdx.x * BM;

    const float* qb = g_q + (size_t)b * NTOK * BD;
    const __nv_bfloat16* khb = g_khi + (size_t)b * BD * NTOK;
    const __nv_bfloat16* klb = g_klo + (size_t)b * BD * NTOK;
    const __nv_bfloat16* vb  = g_vb + (size_t)b * NTOK * CC;

    // ---- prologue: stage tile 0 K hi/lo ([d][key] rows) + V (token rows)
    {
        int d = tid >> 3, g16 = tid & 7;
        cp16s(sb + KH_OFF + (u32)(d * K_STRB + g16 * 16), khb + (size_t)d * NTOK + g16 * 8);
        cp16s(sb + KL_OFF + (u32)(d * K_STRB + g16 * 16), klb + (size_t)d * NTOK + g16 * 8);
    }
#pragma unroll
    for (int it = 0; it < 8; ++it) {
        int e = tid + it * 128;
        int k = e >> 4, c16 = e & 15;
        cp16s(sb + V_OFF + (u32)(k * V_STRB + c16 * 16), vb + (size_t)k * CC + c16 * 8);
    }
    CP_COMMIT();

    // ---- Q: fp32 -> bf16 hi/lo rows in smem
#pragma unroll
    for (int it = 0; it < 8; ++it) {
        int e = tid + it * 128;
        int tok = e >> 4, d = e & 15;
        float q = qb[(size_t)(i0 + tok) * BD + d];
        __nv_bfloat16 qh = __float2bfloat16(q);
        float qrem = q - __bfloat162float(qh);
        *(__nv_bfloat16*)(smb + QH_OFF + tok * Q_STRB + d * 2) = qh;
        *(__nv_bfloat16*)(smb + QL_OFF + tok * Q_STRB + d * 2) = __float2bfloat16(qrem);
    }
    __syncthreads();

    // ldmatrix lane addressing (constant per thread)
    int a_row  = (lane & 7) + ((lane >> 3) & 1) * 8;
    int a_csel = ((lane >> 4) & 1) * 16;
    int b_krow = (lane & 7) + ((lane >> 3) & 1) * 8;
    int b_csel = ((lane >> 4) & 1) * 16;

    // ---- Q A-fragments (loop-invariant)
    u32 Ah0, Ah1, Ah2, Ah3, Al0, Al1, Al2, Al3;
    LDSM_X4(Ah0, Ah1, Ah2, Ah3, sb + QH_OFF + (u32)((warp * 16 + a_row) * Q_STRB + a_csel));
    LDSM_X4(Al0, Al1, Al2, Al3, sb + QL_OFF + (u32)((warp * 16 + a_row) * Q_STRB + a_csel));

    float acc[16][4];                        // 16 n-blocks x m16n8 fragment
#pragma unroll
    for (int nb = 0; nb < 16; ++nb)
#pragma unroll
        for (int r = 0; r < 4; ++r) acc[nb][r] = 0.f;
    float lp0 = 0.f, lp1 = 0.f;              // per-thread partial row sums

    for (int t = 0; t < NT; ++t) {
        __syncthreads();   // prior tile's K/V reads done before overwrite

        if (t + 1 < NT) {
            int j1 = (t + 1) * BN;
            u32 buf = (u32)((t + 1) & 1);
            {
                int d = tid >> 3, g16 = tid & 7;
                cp16s(sb + KH_OFF + buf * K_BUFB + (u32)(d * K_STRB + g16 * 16),
                      khb + (size_t)d * NTOK + j1 + g16 * 8);
                cp16s(sb + KL_OFF + buf * K_BUFB + (u32)(d * K_STRB + g16 * 16),
                      klb + (size_t)d * NTOK + j1 + g16 * 8);
            }
#pragma unroll
            for (int it = 0; it < 8; ++it) {
                int e = tid + it * 128;
                int k = e >> 4, c16 = e & 15;
                cp16s(sb + V_OFF + buf * V_BUFB + (u32)(k * V_STRB + c16 * 16),
                      vb + (size_t)(j1 + k) * CC + c16 * 8);
            }
        }
        CP_COMMIT();
        CP_WAIT1();        // tile t resident
        __syncthreads();

        // ---- QK on tensor cores: s = Qh*Kh + Ql*Kh + Qh*Kl (bf16x3)
        // term-major issue order: dependent MMAs on each c[] are 8 apart
        u32 khbase = sb + KH_OFF + (u32)((t & 1) * K_BUFB) + (u32)(b_krow * K_STRB + b_csel);
        u32 klbase = sb + KL_OFF + (u32)((t & 1) * K_BUFB) + (u32)(b_krow * K_STRB + b_csel);
        u32 H[4][4], L[4][4];
#pragma unroll
        for (int g = 0; g < 4; ++g) {
            LDSM_X4T(H[g][0], H[g][1], H[g][2], H[g][3], khbase + g * 32);
            LDSM_X4T(L[g][0], L[g][1], L[g][2], L[g][3], klbase + g * 32);
        }
        float c[8][4];
#pragma unroll
        for (int nb = 0; nb < 8; ++nb)
#pragma unroll
            for (int r = 0; r < 4; ++r) c[nb][r] = 0.f;
#pragma unroll
        for (int g = 0; g < 4; ++g) {
            MMA_BF16(c[2*g][0], c[2*g][1], c[2*g][2], c[2*g][3],
                     Ah0, Ah1, Ah2, Ah3, H[g][0], H[g][1]);
            MMA_BF16(c[2*g+1][0], c[2*g+1][1], c[2*g+1][2], c[2*g+1][3],
                     Ah0, Ah1, Ah2, Ah3, H[g][2], H[g][3]);
        }
#pragma unroll
        for (int g = 0; g < 4; ++g) {
            MMA_BF16(c[2*g][0], c[2*g][1], c[2*g][2], c[2*g][3],
                     Al0, Al1, Al2, Al3, H[g][0], H[g][1]);
            MMA_BF16(c[2*g+1][0], c[2*g+1][1], c[2*g+1][2], c[2*g+1][3],
                     Al0, Al1, Al2, Al3, H[g][2], H[g][3]);
        }
#pragma unroll
        for (int g = 0; g < 4; ++g) {
            MMA_BF16(c[2*g][0], c[2*g][1], c[2*g][2], c[2*g][3],
                     Ah0, Ah1, Ah2, Ah3, L[g][0], L[g][1]);
            MMA_BF16(c[2*g+1][0], c[2*g+1][1], c[2*g+1][2], c[2*g+1][3],
                     Ah0, Ah1, Ah2, Ah3, L[g][2], L[g][3]);
        }

        // ---- exp + pack P directly into A-fragments (no smem round-trip)
        u32 aP[4][4];
#pragma unroll
        for (int nb = 0; nb < 8; ++nb) {
            float p0 = __expf(c[nb][0]);
            float p1 = __expf(c[nb][1]);
            float p2 = __expf(c[nb][2]);
            float p3 = __expf(c[nb][3]);
            lp0 += p0 + p1;
            lp1 += p2 + p3;
            int ks = nb >> 1;
            if ((nb & 1) == 0) {
                aP[ks][0] = cvt2bf(p0, p1);
                aP[ks][1] = cvt2bf(p2, p3);
            } else {
                aP[ks][2] = cvt2bf(p0, p1);
                aP[ks][3] = cvt2bf(p2, p3);
            }
        }

        // ---- PV: ks outer / channel inner -> 16 independent MMAs per round
        u32 vbase = sb + V_OFF + (u32)((t & 1) * V_BUFB);
#pragma unroll
        for (int ks = 0; ks < 4; ++ks) {
            u32 krowoff = (u32)((ks * 16 + b_krow) * V_STRB + b_csel);
#pragma unroll
            for (int nbp = 0; nbp < 8; ++nbp) {
                u32 b0, b1, b2, b3;
                LDSM_X4T(b0, b1, b2, b3, vbase + krowoff + (u32)(nbp * 32));
                MMA_BF16(acc[nbp * 2][0], acc[nbp * 2][1], acc[nbp * 2][2], acc[nbp * 2][3],
                         aP[ks][0], aP[ks][1], aP[ks][2], aP[ks][3], b0, b1);
                MMA_BF16(acc[nbp * 2 + 1][0], acc[nbp * 2 + 1][1],
                         acc[nbp * 2 + 1][2], acc[nbp * 2 + 1][3],
                         aP[ks][0], aP[ks][1], aP[ks][2], aP[ks][3], b2, b3);
            }
        }
    }

    // ---- l: quad reduce (rows r0/r0+8 shared by lanes 4k..4k+3)
    lp0 += __shfl_xor_sync(0xffffffffu, lp0, 1, 4);
    lp0 += __shfl_xor_sync(0xffffffffu, lp0, 2, 4);
    lp1 += __shfl_xor_sync(0xffffffffu, lp1, 1, 4);
    lp1 += __shfl_xor_sync(0xffffffffu, lp1, 2, 4);

    // ---- epilogue: out = gamma * acc / l + xh
    {
        float g = gamma[0];
        float inv0 = g / lp0;
        float inv1 = g / lp1;
        int r0 = warp * 16 + (lane >> 2);
#pragma unroll
        for (int nb = 0; nb < 16; ++nb) {
            int ch = nb * 8 + (lane & 3) * 2;
            size_t g00 = ((size_t)(b * CC + ch)) * NTOK + i0 + r0;
            size_t g01 = g00 + NTOK;
            out[g00]     = acc[nb][0] * inv0 + xh[g00];
            out[g01]     = acc[nb][1] * inv0 + xh[g01];
            out[g00 + 8] = acc[nb][2] * inv1 + xh[g00 + 8];
            out[g01 + 8] = acc[nb][3] * inv1 + xh[g01 + 8];
        }
    }
}

// ---------------------------------------------------------------------------
extern "C" void kernel_launch(void* const* d_in, const int* in_sizes, int n_in,
                              void* d_out, int out_size)
{
    const float* x     = (const float*)d_in[0];
    const float* xh    = (const float*)d_in[1];
    const float* Wq    = (const float*)d_in[2];
    const float* bq    = (const float*)d_in[3];
    const float* Wk    = (const float*)d_in[4];
    const float* bk    = (const float*)d_in[5];
    const float* Wv    = (const float*)d_in[6];
    const float* bv    = (const float*)d_in[7];
    const float* gamma = (const float*)d_in[8];
    float* out = (float*)d_out;

    (void)in_sizes; (void)n_in; (void)out_size;

    cudaFuncSetAttribute(flash_kernel, cudaFuncAttributeMaxDynamicSharedMemorySize, SMEM_BYTES);

    proj_kernel<<<dim3(16 + NTOK / 64, NB), 256>>>(x, Wq, bq, Wk, bk, xh, Wv, bv);
    flash_kernel<<<dim3(NTOK / BM, NB), 128, SMEM_BYTES>>>(xh, gamma, out);
}